// round 1
// baseline (speedup 1.0000x reference)
#include <cuda_runtime.h>

#define NN 100000
#define NE 1200000
#define D 64
#define NL 3
#define NM 5000
#define NO 24
#define BN_EPS 1e-5f

// ---------------- scratch (device globals; no allocation allowed) ----------------
__device__ __align__(128) float g_X0 [NN * D];          // embedding out / JK out
__device__ __align__(128) float g_AGG[NN * D];          // neighbor sums
__device__ __align__(128) float g_T  [NN * D];          // GEMM1 out (pre-BN)
__device__ __align__(128) float g_XS [NL * NN * D];     // per-layer outputs for JK
__device__ __align__(128) float g_G  [NM * D];          // pooled per-mol
__device__ __align__(128) float g_TG [NM * D];          // ffn1 out (pre-BN)
__device__ __align__(128) float g_stats[2 * D];         // col sum, sumsq
__device__ __align__(128) float g_bnab [2 * D];         // per-col scale a, shift b
__device__ __align__(128) float g_Wc [D * NO];          // ffn_W2 @ out_W
__device__ __align__(128) float g_bc [NO];              // b2 @ out_W + out_b

__device__ __forceinline__ void red_add_f4(float4* p, float4 v) {
    atomicAdd(p, v);   // sm_90+ native vector atomic add
}

// ---------------- kernels ----------------

__global__ void k_zero(float4* p, int n4) {
    int t = blockIdx.x * blockDim.x + threadIdx.x;
    if (t < n4) p[t] = make_float4(0.f, 0.f, 0.f, 0.f);
}

__global__ void k_embed(const int* __restrict__ atom_ids, const float* __restrict__ embW) {
    int t = blockIdx.x * blockDim.x + threadIdx.x;
    if (t >= NN * 16) return;
    int n = t >> 4, c = (t & 15) << 2;
    int a = __ldg(atom_ids + n);
    *(float4*)(g_X0 + (size_t)n * D + c) = *(const float4*)(embW + (size_t)a * D + c);
}

// agg[dst] += x[src]
__global__ void k_scatter(const float* __restrict__ X, const int* __restrict__ src,
                          const int* __restrict__ dst) {
    unsigned t = blockIdx.x * 256u + threadIdx.x;
    if (t >= (unsigned)NE * 16u) return;
    unsigned e = t >> 4, c = (t & 15u) << 2;
    int s = __ldg(src + e), d = __ldg(dst + e);
    float4 v = *(const float4*)(X + (size_t)s * D + c);
    red_add_f4((float4*)(g_AGG + (size_t)d * D + c), v);
}

// O = (X + A) @ W + b        (rows x 64) @ (64 x 64)
__global__ __launch_bounds__(256) void k_gemm_add(
    const float* __restrict__ X, const float* __restrict__ A,
    const float* __restrict__ W, const float* __restrict__ b,
    float* __restrict__ O, int rows)
{
    __shared__ float4 Ws[D * 16];
    __shared__ float  bs[D];
    int tid = threadIdx.x;
    for (int i = tid; i < D * 16; i += 256) Ws[i] = ((const float4*)W)[i];
    if (tid < D) bs[tid] = b[tid];
    __syncthreads();
    int row = blockIdx.x * 256 + tid;
    if (row >= rows) return;
    float4 acc[16];
    #pragma unroll
    for (int c = 0; c < 16; c++)
        acc[c] = make_float4(bs[4*c], bs[4*c+1], bs[4*c+2], bs[4*c+3]);
    const float4* xr = (const float4*)(X + (size_t)row * D);
    const float4* ar = (const float4*)(A + (size_t)row * D);
    #pragma unroll 4
    for (int k4 = 0; k4 < 16; k4++) {
        float4 xv = xr[k4], av = ar[k4];
        float h[4] = {xv.x + av.x, xv.y + av.y, xv.z + av.z, xv.w + av.w};
        #pragma unroll
        for (int j = 0; j < 4; j++) {
            #pragma unroll
            for (int c = 0; c < 16; c++) {
                float4 w = Ws[(k4*4 + j)*16 + c];
                acc[c].x += h[j]*w.x; acc[c].y += h[j]*w.y;
                acc[c].z += h[j]*w.z; acc[c].w += h[j]*w.w;
            }
        }
    }
    float4* orow = (float4*)(O + (size_t)row * D);
    #pragma unroll
    for (int c = 0; c < 16; c++) orow[c] = acc[c];
}

// O = relu( relu(T*a + ab) @ W + b )   (BN apply fused on load, relu on store)
__global__ __launch_bounds__(256) void k_gemm_bn(
    const float* __restrict__ T, const float* __restrict__ W,
    const float* __restrict__ b, float* __restrict__ O, int rows)
{
    __shared__ float4 Ws[D * 16];
    __shared__ float  bs[D], sa[D], sb[D];
    int tid = threadIdx.x;
    for (int i = tid; i < D * 16; i += 256) Ws[i] = ((const float4*)W)[i];
    if (tid < D) { bs[tid] = b[tid]; sa[tid] = g_bnab[tid]; sb[tid] = g_bnab[D + tid]; }
    __syncthreads();
    int row = blockIdx.x * 256 + tid;
    if (row >= rows) return;
    float4 acc[16];
    #pragma unroll
    for (int c = 0; c < 16; c++)
        acc[c] = make_float4(bs[4*c], bs[4*c+1], bs[4*c+2], bs[4*c+3]);
    const float4* tr = (const float4*)(T + (size_t)row * D);
    #pragma unroll 4
    for (int k4 = 0; k4 < 16; k4++) {
        float4 tv = tr[k4];
        float h[4];
        h[0] = fmaxf(tv.x * sa[4*k4+0] + sb[4*k4+0], 0.f);
        h[1] = fmaxf(tv.y * sa[4*k4+1] + sb[4*k4+1], 0.f);
        h[2] = fmaxf(tv.z * sa[4*k4+2] + sb[4*k4+2], 0.f);
        h[3] = fmaxf(tv.w * sa[4*k4+3] + sb[4*k4+3], 0.f);
        #pragma unroll
        for (int j = 0; j < 4; j++) {
            #pragma unroll
            for (int c = 0; c < 16; c++) {
                float4 w = Ws[(k4*4 + j)*16 + c];
                acc[c].x += h[j]*w.x; acc[c].y += h[j]*w.y;
                acc[c].z += h[j]*w.z; acc[c].w += h[j]*w.w;
            }
        }
    }
    float4* orow = (float4*)(O + (size_t)row * D);
    #pragma unroll
    for (int c = 0; c < 16; c++) {
        acc[c].x = fmaxf(acc[c].x, 0.f); acc[c].y = fmaxf(acc[c].y, 0.f);
        acc[c].z = fmaxf(acc[c].z, 0.f); acc[c].w = fmaxf(acc[c].w, 0.f);
        orow[c] = acc[c];
    }
}

// O = X @ W + b    (plain, no transform)
__global__ __launch_bounds__(256) void k_gemm_plain(
    const float* __restrict__ X, const float* __restrict__ W,
    const float* __restrict__ b, float* __restrict__ O, int rows)
{
    __shared__ float4 Ws[D * 16];
    __shared__ float  bs[D];
    int tid = threadIdx.x;
    for (int i = tid; i < D * 16; i += 256) Ws[i] = ((const float4*)W)[i];
    if (tid < D) bs[tid] = b[tid];
    __syncthreads();
    int row = blockIdx.x * 256 + tid;
    if (row >= rows) return;
    float4 acc[16];
    #pragma unroll
    for (int c = 0; c < 16; c++)
        acc[c] = make_float4(bs[4*c], bs[4*c+1], bs[4*c+2], bs[4*c+3]);
    const float4* xr = (const float4*)(X + (size_t)row * D);
    #pragma unroll 4
    for (int k4 = 0; k4 < 16; k4++) {
        float4 xv = xr[k4];
        float h[4] = {xv.x, xv.y, xv.z, xv.w};
        #pragma unroll
        for (int j = 0; j < 4; j++) {
            #pragma unroll
            for (int c = 0; c < 16; c++) {
                float4 w = Ws[(k4*4 + j)*16 + c];
                acc[c].x += h[j]*w.x; acc[c].y += h[j]*w.y;
                acc[c].z += h[j]*w.z; acc[c].w += h[j]*w.w;
            }
        }
    }
    float4* orow = (float4*)(O + (size_t)row * D);
    #pragma unroll
    for (int c = 0; c < 16; c++) orow[c] = acc[c];
}

// column sums / sumsq into g_stats (atomic partials)
__global__ void k_bnstats(const float* __restrict__ T, int rows) {
    int c = threadIdx.x & 63;
    int sub = threadIdx.x >> 6;                // 0..3
    float s = 0.f, ss = 0.f;
    for (int r = blockIdx.x * 4 + sub; r < rows; r += gridDim.x * 4) {
        float v = T[(size_t)r * D + c];
        s += v; ss += v * v;
    }
    __shared__ float sh[512];
    sh[threadIdx.x] = s; sh[256 + threadIdx.x] = ss;
    __syncthreads();
    if (threadIdx.x < 64) {
        float S  = sh[c]       + sh[c+64]       + sh[c+128]       + sh[c+192];
        float SS = sh[256+c]   + sh[256+c+64]   + sh[256+c+128]   + sh[256+c+192];
        atomicAdd(&g_stats[c], S);
        atomicAdd(&g_stats[D + c], SS);
    }
}

__global__ void k_bnparam(const float* __restrict__ gg, const float* __restrict__ be,
                          float inv_n) {
    int c = threadIdx.x;
    float mu  = g_stats[c] * inv_n;
    float var = g_stats[D + c] * inv_n - mu * mu;
    float rs  = rsqrtf(var + BN_EPS);
    float a   = rs * gg[c];
    g_bnab[c]     = a;
    g_bnab[D + c] = be[c] - mu * a;
}

// JK: O = concat(XS[0..2]) @ jkW + jkb     (rows x 192) @ (192 x 64)
__global__ __launch_bounds__(256) void k_jk(
    const float* __restrict__ jkW, const float* __restrict__ jkb,
    float* __restrict__ O, int rows)
{
    __shared__ float4 Ws[3 * D * 16];          // 48 KB exactly
    int tid = threadIdx.x;
    for (int i = tid; i < 3 * D * 16; i += 256) Ws[i] = ((const float4*)jkW)[i];
    __syncthreads();
    int row = blockIdx.x * 256 + tid;
    if (row >= rows) return;
    float4 acc[16];
    const float4* jb4 = (const float4*)jkb;
    #pragma unroll
    for (int c = 0; c < 16; c++) acc[c] = jb4[c];
    #pragma unroll
    for (int l = 0; l < NL; l++) {
        const float4* xr = (const float4*)(g_XS + ((size_t)l * NN + row) * D);
        #pragma unroll 4
        for (int k4 = 0; k4 < 16; k4++) {
            float4 xv = xr[k4];
            float h[4] = {xv.x, xv.y, xv.z, xv.w};
            #pragma unroll
            for (int j = 0; j < 4; j++) {
                #pragma unroll
                for (int c = 0; c < 16; c++) {
                    float4 w = Ws[((l*64 + k4*4 + j))*16 + c];
                    acc[c].x += h[j]*w.x; acc[c].y += h[j]*w.y;
                    acc[c].z += h[j]*w.z; acc[c].w += h[j]*w.w;
                }
            }
        }
    }
    float4* orow = (float4*)(O + (size_t)row * D);
    #pragma unroll
    for (int c = 0; c < 16; c++) orow[c] = acc[c];
}

// g_G[mol] += XJ[node]
__global__ void k_pool(const float* __restrict__ XJ, const int* __restrict__ mol) {
    unsigned t = blockIdx.x * 256u + threadIdx.x;
    if (t >= (unsigned)NN * 16u) return;
    unsigned n = t >> 4, c = (t & 15u) << 2;
    int m = __ldg(mol + n);
    float4 v = *(const float4*)(XJ + (size_t)n * D + c);
    red_add_f4((float4*)(g_G + (size_t)m * D + c), v);
}

// Wc = ffn_W2 @ out_W ; bc = b2 @ out_W + out_b
__global__ void k_combine(const float* __restrict__ W2, const float* __restrict__ oW,
                          const float* __restrict__ b2, const float* __restrict__ ob) {
    int idx = blockIdx.x * blockDim.x + threadIdx.x;
    if (idx < D * NO) {
        int k = idx / NO, o = idx % NO;
        float s = 0.f;
        for (int j = 0; j < D; j++) s += W2[k * D + j] * oW[j * NO + o];
        g_Wc[idx] = s;
    }
    if (idx < NO) {
        float s = ob[idx];
        for (int j = 0; j < D; j++) s += b2[j] * oW[j * NO + idx];
        g_bc[idx] = s;
    }
}

// out = relu(TG*a + b) @ Wc + bc      (rows x 64) @ (64 x 24)
__global__ __launch_bounds__(256) void k_final(float* __restrict__ out, int rows) {
    __shared__ float Ws[D * NO];
    __shared__ float bcs[NO], sa[D], sb[D];
    int tid = threadIdx.x;
    for (int i = tid; i < D * NO; i += 256) Ws[i] = g_Wc[i];
    if (tid < NO) bcs[tid] = g_bc[tid];
    if (tid < D) { sa[tid] = g_bnab[tid]; sb[tid] = g_bnab[D + tid]; }
    __syncthreads();
    int row = blockIdx.x * 256 + tid;
    if (row >= rows) return;
    float acc[NO];
    #pragma unroll
    for (int o = 0; o < NO; o++) acc[o] = bcs[o];
    const float* tr = g_TG + (size_t)row * D;
    for (int k = 0; k < D; k++) {
        float h = fmaxf(tr[k] * sa[k] + sb[k], 0.f);
        #pragma unroll
        for (int o = 0; o < NO; o++) acc[o] += h * Ws[k * NO + o];
    }
    float* orow = out + (size_t)row * NO;
    #pragma unroll
    for (int o = 0; o < NO; o++) orow[o] = acc[o];
}

// ---------------- host ----------------
extern "C" void kernel_launch(void* const* d_in, const int* in_sizes, int n_in,
                              void* d_out, int out_size)
{
    const int*   atom_ids = (const int*)  d_in[0];
    const int*   edge     = (const int*)  d_in[1];
    const int*   mol_ids  = (const int*)  d_in[2];
    const float* emb_W    = (const float*)d_in[3];
    const float* gin_W1   = (const float*)d_in[4];
    const float* gin_b1   = (const float*)d_in[5];
    const float* gin_g1   = (const float*)d_in[6];
    const float* gin_be1  = (const float*)d_in[7];
    const float* gin_W2   = (const float*)d_in[8];
    const float* gin_b2   = (const float*)d_in[9];
    const float* jk_W     = (const float*)d_in[10];
    const float* jk_b     = (const float*)d_in[11];
    const float* ffn_W1   = (const float*)d_in[12];
    const float* ffn_b1   = (const float*)d_in[13];
    const float* ffn_g    = (const float*)d_in[14];
    const float* ffn_be   = (const float*)d_in[15];
    const float* ffn_W2   = (const float*)d_in[16];
    const float* ffn_b2   = (const float*)d_in[17];
    const float* out_W    = (const float*)d_in[18];
    const float* out_b    = (const float*)d_in[19];
    float* out = (float*)d_out;

    const int* src = edge;
    const int* dst = edge + NE;

    float *X0, *AGG, *T, *XS, *G, *TG, *stats;
    cudaGetSymbolAddress((void**)&X0,    g_X0);
    cudaGetSymbolAddress((void**)&AGG,   g_AGG);
    cudaGetSymbolAddress((void**)&T,     g_T);
    cudaGetSymbolAddress((void**)&XS,    g_XS);
    cudaGetSymbolAddress((void**)&G,     g_G);
    cudaGetSymbolAddress((void**)&TG,    g_TG);
    cudaGetSymbolAddress((void**)&stats, g_stats);

    k_embed<<<(NN*16 + 255)/256, 256>>>(atom_ids, emb_W);

    for (int l = 0; l < NL; l++) {
        const float* xin = (l == 0) ? X0 : XS + (size_t)(l-1) * NN * D;
        k_zero<<<(NN*D/4 + 255)/256, 256>>>((float4*)AGG, NN*D/4);
        k_scatter<<<(NE*16 + 255)/256, 256>>>(xin, src, dst);
        k_gemm_add<<<(NN + 255)/256, 256>>>(xin, AGG, gin_W1 + (size_t)l*D*D,
                                            gin_b1 + l*D, T, NN);
        k_zero<<<1, 64>>>((float4*)stats, 2*D/4);
        k_bnstats<<<296, 256>>>(T, NN);
        k_bnparam<<<1, D>>>(gin_g1 + l*D, gin_be1 + l*D, 1.0f / NN);
        k_gemm_bn<<<(NN + 255)/256, 256>>>(T, gin_W2 + (size_t)l*D*D,
                                           gin_b2 + l*D, XS + (size_t)l*NN*D, NN);
    }

    k_jk<<<(NN + 255)/256, 256>>>(jk_W, jk_b, X0, NN);   // JK out reuses X0

    k_zero<<<(NM*D/4 + 255)/256, 256>>>((float4*)G, NM*D/4);
    k_pool<<<(NN*16 + 255)/256, 256>>>(X0, mol_ids);

    k_gemm_plain<<<(NM + 255)/256, 256>>>(G, ffn_W1, ffn_b1, TG, NM);
    k_zero<<<1, 64>>>((float4*)stats, 2*D/4);
    k_bnstats<<<296, 256>>>(TG, NM);
    k_bnparam<<<1, D>>>(ffn_g, ffn_be, 1.0f / NM);

    k_combine<<<6, 256>>>(ffn_W2, out_W, ffn_b2, out_b);
    k_final<<<(NM + 255)/256, 256>>>(out, NM);
}

// round 2
// speedup vs baseline: 1.1382x; 1.1382x over previous
#include <cuda_runtime.h>

#define NN 100000
#define NE 1200000
#define D 64
#define NL 3
#define NM 5000
#define NO 24
#define BN_EPS 1e-5f
#define NB_SCAN ((NN + 1023) / 1024)

typedef unsigned long long ull;

// ---------------- scratch (device globals; no allocation allowed) ----------------
__device__ __align__(128) float g_X0 [NN * D];          // embedding out / JK out
__device__ __align__(128) float g_H  [NN * D];          // x + agg
__device__ __align__(128) float g_T  [NN * D];          // GEMM1 out (pre-BN)
__device__ __align__(128) float g_XS [NL * NN * D];     // per-layer outputs for JK
__device__ __align__(128) float g_G  [NM * D];          // pooled per-mol
__device__ __align__(128) float g_TG [NM * D];          // ffn1 out (pre-BN)
__device__ __align__(128) float g_stats[2 * D];         // col sum, sumsq
__device__ __align__(128) float g_bnab [2 * D];         // per-col scale a, shift b
__device__ __align__(128) float g_Wc [D * NO];          // ffn_W2 @ out_W
__device__ __align__(128) float g_bc [NO];
// CSR scratch
__device__ __align__(128) int g_deg   [NN];
__device__ __align__(128) int g_cur   [NN];
__device__ __align__(128) int g_rowptr[NN + 1];
__device__ __align__(128) int g_csr   [NE];
__device__ __align__(128) int g_bsum  [NB_SCAN];
__device__ __align__(128) int g_boff  [NB_SCAN];
__device__ __align__(128) int g_molptr[NM + 1];

// ---------------- f32x2 helpers ----------------
__device__ __forceinline__ ull ffma2(ull a, ull b, ull c) {
    ull d; asm("fma.rn.f32x2 %0, %1, %2, %3;" : "=l"(d) : "l"(a), "l"(b), "l"(c));
    return d;
}
__device__ __forceinline__ ull pack2(float x) {
    ull r; asm("mov.b64 %0, {%1, %1};" : "=l"(r) : "f"(x)); return r;
}
__device__ __forceinline__ float2 u2f(ull v) {
    float2 f; asm("mov.b64 {%0, %1}, %2;" : "=f"(f.x), "=f"(f.y) : "l"(v)); return f;
}
__device__ __forceinline__ ull f2u(float x, float y) {
    ull v; asm("mov.b64 %0, {%1, %2};" : "=l"(v) : "f"(x), "f"(y)); return v;
}

// ---------------- small utility kernels ----------------
__global__ void k_zero_f4(float4* p, int n4) {
    int t = blockIdx.x * blockDim.x + threadIdx.x;
    if (t < n4) p[t] = make_float4(0.f, 0.f, 0.f, 0.f);
}
__global__ void k_zero_i(int* p, int n) {
    int t = blockIdx.x * blockDim.x + threadIdx.x;
    if (t < n) p[t] = 0;
}

__global__ void k_embed(const int* __restrict__ atom_ids, const float* __restrict__ embW) {
    int t = blockIdx.x * blockDim.x + threadIdx.x;
    if (t >= NN * 16) return;
    int n = t >> 4, c = (t & 15) << 2;
    int a = __ldg(atom_ids + n);
    *(float4*)(g_X0 + (size_t)n * D + c) = *(const float4*)(embW + (size_t)a * D + c);
}

// ---------------- CSR build ----------------
__global__ void k_count(const int* __restrict__ dst) {
    int t = blockIdx.x * blockDim.x + threadIdx.x;
    if (t < NE) atomicAdd(&g_deg[__ldg(dst + t)], 1);
}
__global__ void k_scan_block() {
    __shared__ int sh[1024];
    int b = blockIdx.x, tid = threadIdx.x;
    int i = b * 1024 + tid;
    int v = (i < NN) ? g_deg[i] : 0;
    sh[tid] = v; __syncthreads();
    #pragma unroll
    for (int off = 1; off < 1024; off <<= 1) {
        int t2 = (tid >= off) ? sh[tid - off] : 0;
        __syncthreads();
        sh[tid] += t2;
        __syncthreads();
    }
    if (i < NN) g_rowptr[i + 1] = sh[tid];
    if (tid == 1023) g_bsum[b] = sh[1023];
}
__global__ void k_scan_tops() {
    if (threadIdx.x == 0) {
        int run = 0;
        for (int b = 0; b < NB_SCAN; b++) { g_boff[b] = run; run += g_bsum[b]; }
    }
}
__global__ void k_scan_add() {
    int i = blockIdx.x * blockDim.x + threadIdx.x;
    if (i == 0) g_rowptr[0] = 0;
    if (i < NN) g_rowptr[i + 1] += g_boff[i >> 10];
}
__global__ void k_fill(const int* __restrict__ src, const int* __restrict__ dst) {
    int t = blockIdx.x * blockDim.x + threadIdx.x;
    if (t >= NE) return;
    int d = __ldg(dst + t);
    int pos = g_rowptr[d] + atomicAdd(&g_cur[d], 1);
    g_csr[pos] = __ldg(src + t);
}

// mol boundaries (mol_ids sorted)
__global__ void k_molptr(const int* __restrict__ mol) {
    int t = blockIdx.x * blockDim.x + threadIdx.x;
    if (t >= NN) return;
    int m1 = __ldg(mol + t);
    int m0 = (t == 0) ? -1 : __ldg(mol + t - 1);
    for (int m = m0 + 1; m <= m1; m++) g_molptr[m] = t;
    if (t == NN - 1)
        for (int m = m1 + 1; m <= NM; m++) g_molptr[m] = NN;
}

// ---------------- gather: H[n] = X[n] + sum_{s in N(n)} X[s] ----------------
__global__ __launch_bounds__(256) void k_gather(const float* __restrict__ X) {
    int t = blockIdx.x * 256 + threadIdx.x;
    int node = t >> 4;
    if (node >= NN) return;
    int c = (t & 15) << 2;
    int beg = g_rowptr[node], end = g_rowptr[node + 1];
    float4 acc = *(const float4*)(X + (size_t)node * D + c);
    for (int e = beg; e < end; e++) {
        int s = __ldg(&g_csr[e]);
        float4 v = *(const float4*)(X + (size_t)s * D + c);
        acc.x += v.x; acc.y += v.y; acc.z += v.z; acc.w += v.w;
    }
    *(float4*)(g_H + (size_t)node * D + c) = acc;
}

// ---------------- 64x64 GEMM, 2 rows x 16 cols per thread, f32x2 FMAs ----------
// IN_BN: x <- relu(x*a + b) using g_bnab ; OUT_RELU: relu on store.
template<int IN_BN, int OUT_RELU>
__global__ __launch_bounds__(256) void k_gemm64(
    const float* __restrict__ X, const float* __restrict__ W,
    const float* __restrict__ bias, float* __restrict__ O, int rows)
{
    __shared__ __align__(16) float Ws[D * D];
    __shared__ float ssa[D], ssb[D];
    int tid = threadIdx.x;
    for (int i = tid; i < D * D / 4; i += 256) ((float4*)Ws)[i] = ((const float4*)W)[i];
    if (IN_BN && tid < D) { ssa[tid] = g_bnab[tid]; ssb[tid] = g_bnab[D + tid]; }
    __syncthreads();

    int r0 = blockIdx.x * 128 + (tid & 63) * 2;
    if (r0 >= rows) return;
    int r1 = r0 + 1;                 // rows is even for all our calls
    int cg = tid >> 6;               // 0..3 (16-col group)

    ull a0[8], a1[8];
    const ull* bu = (const ull*)bias;
    #pragma unroll
    for (int q = 0; q < 8; q++) { a0[q] = bu[cg * 8 + q]; a1[q] = a0[q]; }

    const float4* x0p = (const float4*)(X + (size_t)r0 * D);
    const float4* x1p = (const float4*)(X + (size_t)r1 * D);
    const ulonglong2* Wu = (const ulonglong2*)Ws;

    #pragma unroll
    for (int k4 = 0; k4 < 16; k4++) {
        float4 x0 = x0p[k4], x1 = x1p[k4];
        if (IN_BN) {
            float4 sa = *(const float4*)(ssa + k4 * 4);
            float4 sb = *(const float4*)(ssb + k4 * 4);
            x0.x = fmaxf(x0.x * sa.x + sb.x, 0.f); x0.y = fmaxf(x0.y * sa.y + sb.y, 0.f);
            x0.z = fmaxf(x0.z * sa.z + sb.z, 0.f); x0.w = fmaxf(x0.w * sa.w + sb.w, 0.f);
            x1.x = fmaxf(x1.x * sa.x + sb.x, 0.f); x1.y = fmaxf(x1.y * sa.y + sb.y, 0.f);
            x1.z = fmaxf(x1.z * sa.z + sb.z, 0.f); x1.w = fmaxf(x1.w * sa.w + sb.w, 0.f);
        }
        float h0[4] = {x0.x, x0.y, x0.z, x0.w};
        float h1[4] = {x1.x, x1.y, x1.z, x1.w};
        #pragma unroll
        for (int j = 0; j < 4; j++) {
            int k = k4 * 4 + j;
            ull p0 = pack2(h0[j]), p1 = pack2(h1[j]);
            #pragma unroll
            for (int p = 0; p < 4; p++) {
                ulonglong2 w = Wu[k * 16 + cg * 4 + p];
                a0[2*p]   = ffma2(p0, w.x, a0[2*p]);
                a0[2*p+1] = ffma2(p0, w.y, a0[2*p+1]);
                a1[2*p]   = ffma2(p1, w.x, a1[2*p]);
                a1[2*p+1] = ffma2(p1, w.y, a1[2*p+1]);
            }
        }
    }

    ull* o0 = (ull*)O + (size_t)r0 * 32 + cg * 8;
    ull* o1 = (ull*)O + (size_t)r1 * 32 + cg * 8;
    #pragma unroll
    for (int q = 0; q < 8; q++) {
        if (OUT_RELU) {
            float2 f0 = u2f(a0[q]), f1 = u2f(a1[q]);
            o0[q] = f2u(fmaxf(f0.x, 0.f), fmaxf(f0.y, 0.f));
            o1[q] = f2u(fmaxf(f1.x, 0.f), fmaxf(f1.y, 0.f));
        } else {
            o0[q] = a0[q]; o1[q] = a1[q];
        }
    }
}

// JK: O = concat(XS[0..2]) @ jkW + jkb, done in 3 phases of 64 k each
__global__ __launch_bounds__(256) void k_jk(
    const float* __restrict__ jkW, const float* __restrict__ jkb,
    float* __restrict__ O, int rows)
{
    __shared__ __align__(16) float Ws[D * D];
    int tid = threadIdx.x;
    int r0 = blockIdx.x * 128 + (tid & 63) * 2;
    int r1 = r0 + 1;
    int cg = tid >> 6;
    bool act = (r0 < rows);

    ull a0[8], a1[8];
    const ull* bu = (const ull*)jkb;
    #pragma unroll
    for (int q = 0; q < 8; q++) { a0[q] = bu[cg * 8 + q]; a1[q] = a0[q]; }

    for (int l = 0; l < NL; l++) {
        __syncthreads();
        for (int i = tid; i < D * D / 4; i += 256)
            ((float4*)Ws)[i] = ((const float4*)(jkW + (size_t)l * D * D))[i];
        __syncthreads();
        if (!act) continue;
        const float4* x0p = (const float4*)(g_XS + ((size_t)l * NN + r0) * D);
        const float4* x1p = (const float4*)(g_XS + ((size_t)l * NN + r1) * D);
        const ulonglong2* Wu = (const ulonglong2*)Ws;
        #pragma unroll
        for (int k4 = 0; k4 < 16; k4++) {
            float4 x0 = x0p[k4], x1 = x1p[k4];
            float h0[4] = {x0.x, x0.y, x0.z, x0.w};
            float h1[4] = {x1.x, x1.y, x1.z, x1.w};
            #pragma unroll
            for (int j = 0; j < 4; j++) {
                int k = k4 * 4 + j;
                ull p0 = pack2(h0[j]), p1 = pack2(h1[j]);
                #pragma unroll
                for (int p = 0; p < 4; p++) {
                    ulonglong2 w = Wu[k * 16 + cg * 4 + p];
                    a0[2*p]   = ffma2(p0, w.x, a0[2*p]);
                    a0[2*p+1] = ffma2(p0, w.y, a0[2*p+1]);
                    a1[2*p]   = ffma2(p1, w.x, a1[2*p]);
                    a1[2*p+1] = ffma2(p1, w.y, a1[2*p+1]);
                }
            }
        }
    }
    if (!act) return;
    ull* o0 = (ull*)O + (size_t)r0 * 32 + cg * 8;
    ull* o1 = (ull*)O + (size_t)r1 * 32 + cg * 8;
    #pragma unroll
    for (int q = 0; q < 8; q++) { o0[q] = a0[q]; o1[q] = a1[q]; }
}

// ---------------- BN statistics ----------------
__global__ void k_bnstats(const float* __restrict__ T, int rows) {
    int c = threadIdx.x & 63;
    int sub = threadIdx.x >> 6;
    float s = 0.f, ss = 0.f;
    for (int r = blockIdx.x * 4 + sub; r < rows; r += gridDim.x * 4) {
        float v = T[(size_t)r * D + c];
        s += v; ss += v * v;
    }
    __shared__ float sh[512];
    sh[threadIdx.x] = s; sh[256 + threadIdx.x] = ss;
    __syncthreads();
    if (threadIdx.x < 64) {
        float S  = sh[c]     + sh[c+64]     + sh[c+128]     + sh[c+192];
        float SS = sh[256+c] + sh[256+c+64] + sh[256+c+128] + sh[256+c+192];
        atomicAdd(&g_stats[c], S);
        atomicAdd(&g_stats[D + c], SS);
    }
}
__global__ void k_bnparam(const float* __restrict__ gg, const float* __restrict__ be,
                          float inv_n) {
    int c = threadIdx.x;
    float mu  = g_stats[c] * inv_n;
    float var = g_stats[D + c] * inv_n - mu * mu;
    float rs  = rsqrtf(var + BN_EPS);
    float a   = rs * gg[c];
    g_bnab[c]     = a;
    g_bnab[D + c] = be[c] - mu * a;
}

// ---------------- segmented pool: G[m] = sum over nodes of mol m ------------
__global__ void k_pool_seg(const float* __restrict__ XJ) {
    int t = blockIdx.x * 256 + threadIdx.x;
    int m = t >> 4;
    if (m >= NM) return;
    int c = (t & 15) << 2;
    int beg = g_molptr[m], end = g_molptr[m + 1];
    float4 acc = make_float4(0.f, 0.f, 0.f, 0.f);
    for (int n = beg; n < end; n++) {
        float4 v = *(const float4*)(XJ + (size_t)n * D + c);
        acc.x += v.x; acc.y += v.y; acc.z += v.z; acc.w += v.w;
    }
    *(float4*)(g_G + (size_t)m * D + c) = acc;
}

// Wc = ffn_W2 @ out_W ; bc = b2 @ out_W + out_b
__global__ void k_combine(const float* __restrict__ W2, const float* __restrict__ oW,
                          const float* __restrict__ b2, const float* __restrict__ ob) {
    int idx = blockIdx.x * blockDim.x + threadIdx.x;
    if (idx < D * NO) {
        int k = idx / NO, o = idx % NO;
        float s = 0.f;
        for (int j = 0; j < D; j++) s += W2[k * D + j] * oW[j * NO + o];
        g_Wc[idx] = s;
    }
    if (idx < NO) {
        float s = ob[idx];
        for (int j = 0; j < D; j++) s += b2[j] * oW[j * NO + idx];
        g_bc[idx] = s;
    }
}

// out = relu(TG*a + b) @ Wc + bc
__global__ __launch_bounds__(256) void k_final(float* __restrict__ out, int rows) {
    __shared__ float Ws[D * NO];
    __shared__ float bcs[NO], sa[D], sb[D];
    int tid = threadIdx.x;
    for (int i = tid; i < D * NO; i += 256) Ws[i] = g_Wc[i];
    if (tid < NO) bcs[tid] = g_bc[tid];
    if (tid < D) { sa[tid] = g_bnab[tid]; sb[tid] = g_bnab[D + tid]; }
    __syncthreads();
    int row = blockIdx.x * 256 + tid;
    if (row >= rows) return;
    float acc[NO];
    #pragma unroll
    for (int o = 0; o < NO; o++) acc[o] = bcs[o];
    const float* tr = g_TG + (size_t)row * D;
    for (int k = 0; k < D; k++) {
        float h = fmaxf(tr[k] * sa[k] + sb[k], 0.f);
        #pragma unroll
        for (int o = 0; o < NO; o++) acc[o] += h * Ws[k * NO + o];
    }
    float* orow = out + (size_t)row * NO;
    #pragma unroll
    for (int o = 0; o < NO; o++) orow[o] = acc[o];
}

// ---------------- host ----------------
extern "C" void kernel_launch(void* const* d_in, const int* in_sizes, int n_in,
                              void* d_out, int out_size)
{
    const int*   atom_ids = (const int*)  d_in[0];
    const int*   edge     = (const int*)  d_in[1];
    const int*   mol_ids  = (const int*)  d_in[2];
    const float* emb_W    = (const float*)d_in[3];
    const float* gin_W1   = (const float*)d_in[4];
    const float* gin_b1   = (const float*)d_in[5];
    const float* gin_g1   = (const float*)d_in[6];
    const float* gin_be1  = (const float*)d_in[7];
    const float* gin_W2   = (const float*)d_in[8];
    const float* gin_b2   = (const float*)d_in[9];
    const float* jk_W     = (const float*)d_in[10];
    const float* jk_b     = (const float*)d_in[11];
    const float* ffn_W1   = (const float*)d_in[12];
    const float* ffn_b1   = (const float*)d_in[13];
    const float* ffn_g    = (const float*)d_in[14];
    const float* ffn_be   = (const float*)d_in[15];
    const float* ffn_W2   = (const float*)d_in[16];
    const float* ffn_b2   = (const float*)d_in[17];
    const float* out_W    = (const float*)d_in[18];
    const float* out_b    = (const float*)d_in[19];
    float* out = (float*)d_out;

    const int* src = edge;
    const int* dst = edge + NE;

    float *X0, *H, *T, *XS, *G, *TG, *stats;
    int *deg, *cur;
    cudaGetSymbolAddress((void**)&X0,    g_X0);
    cudaGetSymbolAddress((void**)&H,     g_H);
    cudaGetSymbolAddress((void**)&T,     g_T);
    cudaGetSymbolAddress((void**)&XS,    g_XS);
    cudaGetSymbolAddress((void**)&G,     g_G);
    cudaGetSymbolAddress((void**)&TG,    g_TG);
    cudaGetSymbolAddress((void**)&stats, g_stats);
    cudaGetSymbolAddress((void**)&deg,   g_deg);
    cudaGetSymbolAddress((void**)&cur,   g_cur);

    // CSR build (once; reused by all 3 layers)
    k_zero_i<<<(NN + 255)/256, 256>>>(deg, NN);
    k_zero_i<<<(NN + 255)/256, 256>>>(cur, NN);
    k_count<<<(NE + 255)/256, 256>>>(dst);
    k_scan_block<<<NB_SCAN, 1024>>>();
    k_scan_tops<<<1, 32>>>();
    k_scan_add<<<(NN + 255)/256, 256>>>();
    k_fill<<<(NE + 255)/256, 256>>>(src, dst);
    k_molptr<<<(NN + 255)/256, 256>>>(mol_ids);

    k_embed<<<(NN*16 + 255)/256, 256>>>(atom_ids, emb_W);

    const int GEMM_GRID = (NN + 127) / 128;
    for (int l = 0; l < NL; l++) {
        const float* xin = (l == 0) ? X0 : XS + (size_t)(l-1) * NN * D;
        k_gather<<<(NN*16 + 255)/256, 256>>>(xin);
        k_gemm64<0,0><<<GEMM_GRID, 256>>>(H, gin_W1 + (size_t)l*D*D, gin_b1 + l*D, T, NN);
        k_zero_f4<<<1, 64>>>((float4*)stats, 2*D/4);
        k_bnstats<<<296, 256>>>(T, NN);
        k_bnparam<<<1, D>>>(gin_g1 + l*D, gin_be1 + l*D, 1.0f / NN);
        k_gemm64<1,1><<<GEMM_GRID, 256>>>(T, gin_W2 + (size_t)l*D*D, gin_b2 + l*D,
                                          XS + (size_t)l*NN*D, NN);
    }

    k_jk<<<GEMM_GRID, 256>>>(jk_W, jk_b, X0, NN);   // JK out reuses X0

    k_pool_seg<<<(NM*16 + 255)/256, 256>>>(X0);

    k_gemm64<0,0><<<(NM + 127)/128, 256>>>(G, ffn_W1, ffn_b1, TG, NM);
    k_zero_f4<<<1, 64>>>((float4*)stats, 2*D/4);
    k_bnstats<<<296, 256>>>(TG, NM);
    k_bnparam<<<1, D>>>(ffn_g, ffn_be, 1.0f / NM);

    k_combine<<<6, 256>>>(ffn_W2, out_W, ffn_b2, out_b);
    k_final<<<(NM + 255)/256, 256>>>(out, NM);
}

// round 5
// speedup vs baseline: 1.1701x; 1.0280x over previous
#include <cuda_runtime.h>

#define NN 100000
#define NE 1200000
#define D 64
#define NL 3
#define NM 5000
#define NO 24
#define BN_EPS 1e-5f
#define NB_SCAN ((NN + 1023) / 1024)
#define HS 68   // smem row stride (floats): 272B = 17*16 (float4-aligned), conflict-free

typedef unsigned long long ull;

// ---------------- scratch ----------------
__device__ __align__(128) float g_X0 [NN * D];
__device__ __align__(128) float g_T  [NN * D];
__device__ __align__(128) float g_XS [NL * NN * D];
__device__ __align__(128) float g_G  [NM * D];
__device__ __align__(128) float g_TG [NM * D];
__device__ __align__(128) float g_stats[2 * D];
__device__ __align__(128) float g_bnab [2 * D];
__device__ __align__(128) int g_deg   [NN];
__device__ __align__(128) int g_cur   [NN];
__device__ __align__(128) int g_rowptr[NN + 1];
__device__ __align__(128) int g_csr   [NE];
__device__ __align__(128) int g_bsum  [NB_SCAN];
__device__ __align__(128) int g_boff  [NB_SCAN];
__device__ __align__(128) int g_molptr[NM + 1];

// ---------------- f32x2 helpers ----------------
__device__ __forceinline__ ull ffma2(ull a, ull b, ull c) {
    ull d; asm("fma.rn.f32x2 %0, %1, %2, %3;" : "=l"(d) : "l"(a), "l"(b), "l"(c));
    return d;
}
__device__ __forceinline__ ull pack2(float x) {
    ull r; asm("mov.b64 %0, {%1, %1};" : "=l"(r) : "f"(x)); return r;
}
__device__ __forceinline__ float2 u2f(ull v) {
    float2 f; asm("mov.b64 {%0, %1}, %2;" : "=f"(f.x), "=f"(f.y) : "l"(v)); return f;
}
__device__ __forceinline__ ull f2u(float x, float y) {
    ull v; asm("mov.b64 %0, {%1, %2};" : "=l"(v) : "f"(x), "f"(y)); return v;
}

// ---------------- init: zero deg, cur, stats ----------------
__global__ void k_init() {
    int t = blockIdx.x * blockDim.x + threadIdx.x;
    if (t < NN) { g_deg[t] = 0; g_cur[t] = 0; }
    if (t < 2 * D) g_stats[t] = 0.f;
}

__global__ void k_embed(const int* __restrict__ atom_ids, const float* __restrict__ embW) {
    int t = blockIdx.x * blockDim.x + threadIdx.x;
    if (t >= NN * 16) return;
    int n = t >> 4, c = (t & 15) << 2;
    int a = __ldg(atom_ids + n);
    *(float4*)(g_X0 + (size_t)n * D + c) = *(const float4*)(embW + (size_t)a * D + c);
}

// ---------------- CSR build ----------------
__global__ void k_count(const int* __restrict__ dst) {
    int t = blockIdx.x * blockDim.x + threadIdx.x;
    if (t < NE) atomicAdd(&g_deg[__ldg(dst + t)], 1);
}
__global__ void k_scan_block() {
    __shared__ int sh[1024];
    int b = blockIdx.x, tid = threadIdx.x;
    int i = b * 1024 + tid;
    int v = (i < NN) ? g_deg[i] : 0;
    sh[tid] = v; __syncthreads();
    #pragma unroll
    for (int off = 1; off < 1024; off <<= 1) {
        int t2 = (tid >= off) ? sh[tid - off] : 0;
        __syncthreads();
        sh[tid] += t2;
        __syncthreads();
    }
    if (i < NN) g_rowptr[i + 1] = sh[tid];
    if (tid == 1023) g_bsum[b] = sh[1023];
}
__global__ void k_scan_tops() {
    int lane = threadIdx.x;                // 128 threads
    int v = (lane < NB_SCAN) ? g_bsum[lane] : 0;
    __shared__ int wsum[4];
    int x = v;
    #pragma unroll
    for (int off = 1; off < 32; off <<= 1) {
        int y = __shfl_up_sync(0xffffffff, x, off);
        if ((lane & 31) >= off) x += y;
    }
    if ((lane & 31) == 31) wsum[lane >> 5] = x;
    __syncthreads();
    int add = 0;
    for (int w = 0; w < (lane >> 5); w++) add += wsum[w];
    int incl = x + add;
    if (lane < NB_SCAN) g_boff[lane] = incl - v;   // exclusive
}
__global__ void k_scan_add() {
    int i = blockIdx.x * blockDim.x + threadIdx.x;
    if (i == 0) g_rowptr[0] = 0;
    if (i < NN) g_rowptr[i + 1] += g_boff[i >> 10];
}
__global__ void k_fill(const int* __restrict__ src, const int* __restrict__ dst) {
    int t = blockIdx.x * blockDim.x + threadIdx.x;
    if (t >= NE) return;
    int d = __ldg(dst + t);
    int pos = g_rowptr[d] + atomicAdd(&g_cur[d], 1);
    g_csr[pos] = __ldg(src + t);
}
__global__ void k_molptr(const int* __restrict__ mol) {
    int t = blockIdx.x * blockDim.x + threadIdx.x;
    if (t >= NN) return;
    int m1 = __ldg(mol + t);
    int m0 = (t == 0) ? -1 : __ldg(mol + t - 1);
    for (int m = m0 + 1; m <= m1; m++) g_molptr[m] = t;
    if (t == NN - 1)
        for (int m = m1 + 1; m <= NM; m++) g_molptr[m] = NN;
}

// ---------------- fused gather + GEMM1 + column-stats (64 rows/block) ----------
__global__ __launch_bounds__(256) void k_gather_gemm(
    const float* __restrict__ X, const float* __restrict__ W,
    const float* __restrict__ bias, float* __restrict__ O, int rows)
{
    __shared__ __align__(16) float Hs[64 * HS];      // 17408 B
    __shared__ __align__(16) float Ws[D * D];        // 16384 B
    int tid = threadIdx.x;

    for (int i = tid; i < D * D / 4; i += 256) ((float4*)Ws)[i] = ((const float4*)W)[i];

    // gather 64 rows (16 threads/node, 4 batches)
    int base = blockIdx.x * 64;
    int c = (tid & 15) << 2;
    #pragma unroll
    for (int b = 0; b < 4; b++) {
        int n = b * 16 + (tid >> 4);          // 0..63
        int node = base + n;
        if (node < rows) {
            int beg = g_rowptr[node], end = g_rowptr[node + 1];
            float4 acc = *(const float4*)(X + (size_t)node * D + c);
            int e = beg;
            for (; e + 1 < end; e += 2) {
                int s0 = __ldg(&g_csr[e]), s1 = __ldg(&g_csr[e + 1]);
                float4 v0 = *(const float4*)(X + (size_t)s0 * D + c);
                float4 v1 = *(const float4*)(X + (size_t)s1 * D + c);
                acc.x += v0.x + v1.x; acc.y += v0.y + v1.y;
                acc.z += v0.z + v1.z; acc.w += v0.w + v1.w;
            }
            if (e < end) {
                int s0 = __ldg(&g_csr[e]);
                float4 v0 = *(const float4*)(X + (size_t)s0 * D + c);
                acc.x += v0.x; acc.y += v0.y; acc.z += v0.z; acc.w += v0.w;
            }
            *(float4*)(Hs + n * HS + c) = acc;
        }
    }
    __syncthreads();

    // GEMM: thread = rows {lane, lane+32} x cols [cg*8, cg*8+8)
    int lane = tid & 31;
    int cg   = tid >> 5;                      // 0..7
    int r0 = base + lane, r1 = r0 + 32;
    bool v0r = (r0 < rows), v1r = (r1 < rows);

    ull a0[4], a1[4];
    const ull* bu = (const ull*)bias;
    #pragma unroll
    for (int q = 0; q < 4; q++) { a0[q] = bu[cg * 4 + q]; a1[q] = a0[q]; }

    const float* x0p = Hs + lane * HS;
    const float* x1p = Hs + (lane + 32) * HS;
    const ulonglong2* Wu = (const ulonglong2*)Ws;   // 16 per k-row

    #pragma unroll
    for (int k4 = 0; k4 < 16; k4++) {
        float4 x0 = *(const float4*)(x0p + k4 * 4);
        float4 x1 = *(const float4*)(x1p + k4 * 4);
        float h0[4] = {x0.x, x0.y, x0.z, x0.w};
        float h1[4] = {x1.x, x1.y, x1.z, x1.w};
        #pragma unroll
        for (int j = 0; j < 4; j++) {
            int k = k4 * 4 + j;
            ull p0 = pack2(h0[j]), p1 = pack2(h1[j]);
            ulonglong2 w0 = Wu[k * 16 + cg * 2];
            ulonglong2 w1 = Wu[k * 16 + cg * 2 + 1];
            a0[0] = ffma2(p0, w0.x, a0[0]); a0[1] = ffma2(p0, w0.y, a0[1]);
            a0[2] = ffma2(p0, w1.x, a0[2]); a0[3] = ffma2(p0, w1.y, a0[3]);
            a1[0] = ffma2(p1, w0.x, a1[0]); a1[1] = ffma2(p1, w0.y, a1[1]);
            a1[2] = ffma2(p1, w1.x, a1[2]); a1[3] = ffma2(p1, w1.y, a1[3]);
        }
    }

    if (v0r) {
        ull* o0 = (ull*)O + (size_t)r0 * 32 + cg * 4;
        #pragma unroll
        for (int q = 0; q < 4; q++) o0[q] = a0[q];
    }
    if (v1r) {
        ull* o1 = (ull*)O + (size_t)r1 * 32 + cg * 4;
        #pragma unroll
        for (int q = 0; q < 4; q++) o1[q] = a1[q];
    }

    // column stats for this thread's 8 cols over its (up to) 2 rows
    float s[8], ss[8];
    #pragma unroll
    for (int q = 0; q < 4; q++) {
        float2 f0 = u2f(a0[q]), f1 = u2f(a1[q]);
        if (!v0r) { f0.x = 0.f; f0.y = 0.f; }
        if (!v1r) { f1.x = 0.f; f1.y = 0.f; }
        s [2*q]   = f0.x + f1.x;  s [2*q+1] = f0.y + f1.y;
        ss[2*q]   = f0.x*f0.x + f1.x*f1.x;
        ss[2*q+1] = f0.y*f0.y + f1.y*f1.y;
    }
    #pragma unroll
    for (int off = 16; off > 0; off >>= 1) {
        #pragma unroll
        for (int q = 0; q < 8; q++) {
            s[q]  += __shfl_xor_sync(0xffffffff, s[q],  off);
            ss[q] += __shfl_xor_sync(0xffffffff, ss[q], off);
        }
    }
    if (lane == 0) {
        #pragma unroll
        for (int q = 0; q < 8; q++) atomicAdd(&g_stats[cg * 8 + q], s[q]);
    } else if (lane == 1) {
        #pragma unroll
        for (int q = 0; q < 8; q++) atomicAdd(&g_stats[D + cg * 8 + q], ss[q]);
    }
}

// ---------------- GEMM2: O = relu( relu(X*a+b) @ W + bias ) ----------------
template<int IN_BN, int OUT_RELU, int STATS>
__global__ __launch_bounds__(256) void k_gemm64(
    const float* __restrict__ X, const float* __restrict__ W,
    const float* __restrict__ bias, float* __restrict__ O, int rows)
{
    __shared__ __align__(16) float Ws[D * D];
    __shared__ float ssa[D], ssb[D];
    int tid = threadIdx.x;
    for (int i = tid; i < D * D / 4; i += 256) ((float4*)Ws)[i] = ((const float4*)W)[i];
    if (IN_BN && tid < D) { ssa[tid] = g_bnab[tid]; ssb[tid] = g_bnab[D + tid]; }
    __syncthreads();

    int r0 = blockIdx.x * 128 + (tid & 63) * 2;
    int r1 = r0 + 1;
    int cg = tid >> 6;
    bool act = (r0 < rows);

    ull a0[8], a1[8];
    const ull* bu = (const ull*)bias;
    #pragma unroll
    for (int q = 0; q < 8; q++) { a0[q] = bu[cg * 8 + q]; a1[q] = a0[q]; }

    if (act) {
        const float4* x0p = (const float4*)(X + (size_t)r0 * D);
        const float4* x1p = (const float4*)(X + (size_t)r1 * D);
        const ulonglong2* Wu = (const ulonglong2*)Ws;
        #pragma unroll
        for (int k4 = 0; k4 < 16; k4++) {
            float4 x0 = x0p[k4], x1 = x1p[k4];
            if (IN_BN) {
                float4 sa = *(const float4*)(ssa + k4 * 4);
                float4 sb = *(const float4*)(ssb + k4 * 4);
                x0.x = fmaxf(x0.x*sa.x+sb.x, 0.f); x0.y = fmaxf(x0.y*sa.y+sb.y, 0.f);
                x0.z = fmaxf(x0.z*sa.z+sb.z, 0.f); x0.w = fmaxf(x0.w*sa.w+sb.w, 0.f);
                x1.x = fmaxf(x1.x*sa.x+sb.x, 0.f); x1.y = fmaxf(x1.y*sa.y+sb.y, 0.f);
                x1.z = fmaxf(x1.z*sa.z+sb.z, 0.f); x1.w = fmaxf(x1.w*sa.w+sb.w, 0.f);
            }
            float h0[4] = {x0.x, x0.y, x0.z, x0.w};
            float h1[4] = {x1.x, x1.y, x1.z, x1.w};
            #pragma unroll
            for (int j = 0; j < 4; j++) {
                int k = k4 * 4 + j;
                ull p0 = pack2(h0[j]), p1 = pack2(h1[j]);
                #pragma unroll
                for (int p = 0; p < 4; p++) {
                    ulonglong2 w = Wu[k * 16 + cg * 4 + p];
                    a0[2*p]   = ffma2(p0, w.x, a0[2*p]);
                    a0[2*p+1] = ffma2(p0, w.y, a0[2*p+1]);
                    a1[2*p]   = ffma2(p1, w.x, a1[2*p]);
                    a1[2*p+1] = ffma2(p1, w.y, a1[2*p+1]);
                }
            }
        }
        ull* o0 = (ull*)O + (size_t)r0 * 32 + cg * 8;
        ull* o1 = (ull*)O + (size_t)r1 * 32 + cg * 8;
        #pragma unroll
        for (int q = 0; q < 8; q++) {
            if (OUT_RELU) {
                float2 f0 = u2f(a0[q]), f1 = u2f(a1[q]);
                o0[q] = f2u(fmaxf(f0.x,0.f), fmaxf(f0.y,0.f));
                o1[q] = f2u(fmaxf(f1.x,0.f), fmaxf(f1.y,0.f));
            } else {
                o0[q] = a0[q]; o1[q] = a1[q];
            }
        }
    }

    if (STATS) {
        float s[16], ssq[16];
        #pragma unroll
        for (int q = 0; q < 8; q++) {
            float2 f0 = u2f(a0[q]), f1 = u2f(a1[q]);
            if (!act) { f0.x = f0.y = f1.x = f1.y = 0.f; }
            s  [2*q]   = f0.x + f1.x;  s  [2*q+1] = f0.y + f1.y;
            ssq[2*q]   = f0.x*f0.x + f1.x*f1.x;
            ssq[2*q+1] = f0.y*f0.y + f1.y*f1.y;
        }
        #pragma unroll
        for (int off = 16; off > 0; off >>= 1) {
            #pragma unroll
            for (int q = 0; q < 16; q++) {
                s[q]   += __shfl_xor_sync(0xffffffff, s[q],   off);
                ssq[q] += __shfl_xor_sync(0xffffffff, ssq[q], off);
            }
        }
        int lane = tid & 31;
        if (lane == 0) {
            #pragma unroll
            for (int q = 0; q < 16; q++) atomicAdd(&g_stats[cg * 16 + q], s[q]);
        } else if (lane == 1) {
            #pragma unroll
            for (int q = 0; q < 16; q++) atomicAdd(&g_stats[D + cg * 16 + q], ssq[q]);
        }
    }
}

__global__ void k_bnparam(const float* __restrict__ gg, const float* __restrict__ be,
                          float inv_n) {
    int c = threadIdx.x;
    float mu  = g_stats[c] * inv_n;
    float var = g_stats[D + c] * inv_n - mu * mu;
    float rs  = rsqrtf(var + BN_EPS);
    float a   = rs * gg[c];
    g_bnab[c]     = a;
    g_bnab[D + c] = be[c] - mu * a;
    g_stats[c] = 0.f; g_stats[D + c] = 0.f;    // ready for next use
}

// JK: O = concat(XS[0..2]) @ jkW + jkb
__global__ __launch_bounds__(256) void k_jk(
    const float* __restrict__ jkW, const float* __restrict__ jkb,
    float* __restrict__ O, int rows)
{
    __shared__ __align__(16) float Ws[D * D];
    int tid = threadIdx.x;
    int r0 = blockIdx.x * 128 + (tid & 63) * 2;
    int r1 = r0 + 1;
    int cg = tid >> 6;
    bool act = (r0 < rows);

    ull a0[8], a1[8];
    const ull* bu = (const ull*)jkb;
    #pragma unroll
    for (int q = 0; q < 8; q++) { a0[q] = bu[cg * 8 + q]; a1[q] = a0[q]; }

    for (int l = 0; l < NL; l++) {
        __syncthreads();
        for (int i = tid; i < D * D / 4; i += 256)
            ((float4*)Ws)[i] = ((const float4*)(jkW + (size_t)l * D * D))[i];
        __syncthreads();
        if (!act) continue;
        const float4* x0p = (const float4*)(g_XS + ((size_t)l * NN + r0) * D);
        const float4* x1p = (const float4*)(g_XS + ((size_t)l * NN + r1) * D);
        const ulonglong2* Wu = (const ulonglong2*)Ws;
        #pragma unroll
        for (int k4 = 0; k4 < 16; k4++) {
            float4 x0 = x0p[k4], x1 = x1p[k4];
            float h0[4] = {x0.x, x0.y, x0.z, x0.w};
            float h1[4] = {x1.x, x1.y, x1.z, x1.w};
            #pragma unroll
            for (int j = 0; j < 4; j++) {
                int k = k4 * 4 + j;
                ull p0 = pack2(h0[j]), p1 = pack2(h1[j]);
                #pragma unroll
                for (int p = 0; p < 4; p++) {
                    ulonglong2 w = Wu[k * 16 + cg * 4 + p];
                    a0[2*p]   = ffma2(p0, w.x, a0[2*p]);
                    a0[2*p+1] = ffma2(p0, w.y, a0[2*p+1]);
                    a1[2*p]   = ffma2(p1, w.x, a1[2*p]);
                    a1[2*p+1] = ffma2(p1, w.y, a1[2*p+1]);
                }
            }
        }
    }
    if (!act) return;
    ull* o0 = (ull*)O + (size_t)r0 * 32 + cg * 8;
    ull* o1 = (ull*)O + (size_t)r1 * 32 + cg * 8;
    #pragma unroll
    for (int q = 0; q < 8; q++) { o0[q] = a0[q]; o1[q] = a1[q]; }
}

// segmented pool
__global__ void k_pool_seg(const float* __restrict__ XJ) {
    int t = blockIdx.x * 256 + threadIdx.x;
    int m = t >> 4;
    if (m >= NM) return;
    int c = (t & 15) << 2;
    int beg = g_molptr[m], end = g_molptr[m + 1];
    float4 acc = make_float4(0.f, 0.f, 0.f, 0.f);
    for (int n = beg; n < end; n++) {
        float4 v = *(const float4*)(XJ + (size_t)n * D + c);
        acc.x += v.x; acc.y += v.y; acc.z += v.z; acc.w += v.w;
    }
    *(float4*)(g_G + (size_t)m * D + c) = acc;
}

// out = relu(TG*a + b) @ (W2 @ oW) + (b2 @ oW + ob)    (combine fused in)
__global__ __launch_bounds__(256) void k_final(
    const float* __restrict__ W2, const float* __restrict__ oW,
    const float* __restrict__ b2, const float* __restrict__ ob,
    float* __restrict__ out, int rows)
{
    __shared__ float Ws[D * NO];
    __shared__ float bcs[NO], sa[D], sb[D];
    int tid = threadIdx.x;
    for (int i = tid; i < D * NO; i += 256) {
        int k = i / NO, o = i % NO;
        float sum = 0.f;
        for (int j = 0; j < D; j++) sum += W2[k * D + j] * oW[j * NO + o];
        Ws[i] = sum;
    }
    if (tid < NO) {
        float sum = ob[tid];
        for (int j = 0; j < D; j++) sum += b2[j] * oW[j * NO + tid];
        bcs[tid] = sum;
    }
    if (tid < D) { sa[tid] = g_bnab[tid]; sb[tid] = g_bnab[D + tid]; }
    __syncthreads();
    int row = blockIdx.x * 256 + tid;
    if (row >= rows) return;
    float acc[NO];
    #pragma unroll
    for (int o = 0; o < NO; o++) acc[o] = bcs[o];
    const float* tr = g_TG + (size_t)row * D;
    for (int k = 0; k < D; k++) {
        float h = fmaxf(tr[k] * sa[k] + sb[k], 0.f);
        #pragma unroll
        for (int o = 0; o < NO; o++) acc[o] += h * Ws[k * NO + o];
    }
    float* orow = out + (size_t)row * NO;
    #pragma unroll
    for (int o = 0; o < NO; o++) orow[o] = acc[o];
}

// ---------------- host ----------------
extern "C" void kernel_launch(void* const* d_in, const int* in_sizes, int n_in,
                              void* d_out, int out_size)
{
    const int*   atom_ids = (const int*)  d_in[0];
    const int*   edge     = (const int*)  d_in[1];
    const int*   mol_ids  = (const int*)  d_in[2];
    const float* emb_W    = (const float*)d_in[3];
    const float* gin_W1   = (const float*)d_in[4];
    const float* gin_b1   = (const float*)d_in[5];
    const float* gin_g1   = (const float*)d_in[6];
    const float* gin_be1  = (const float*)d_in[7];
    const float* gin_W2   = (const float*)d_in[8];
    const float* gin_b2   = (const float*)d_in[9];
    const float* jk_W     = (const float*)d_in[10];
    const float* jk_b     = (const float*)d_in[11];
    const float* ffn_W1   = (const float*)d_in[12];
    const float* ffn_b1   = (const float*)d_in[13];
    const float* ffn_g    = (const float*)d_in[14];
    const float* ffn_be   = (const float*)d_in[15];
    const float* ffn_W2   = (const float*)d_in[16];
    const float* ffn_b2   = (const float*)d_in[17];
    const float* out_W    = (const float*)d_in[18];
    const float* out_b    = (const float*)d_in[19];
    float* out = (float*)d_out;

    const int* src = edge;
    const int* dst = edge + NE;

    float *X0, *T, *XS, *G, *TG;
    cudaGetSymbolAddress((void**)&X0, g_X0);
    cudaGetSymbolAddress((void**)&T,  g_T);
    cudaGetSymbolAddress((void**)&XS, g_XS);
    cudaGetSymbolAddress((void**)&G,  g_G);
    cudaGetSymbolAddress((void**)&TG, g_TG);

    k_init<<<(NN + 255)/256, 256>>>();
    k_count<<<(NE + 255)/256, 256>>>(dst);
    k_scan_block<<<NB_SCAN, 1024>>>();
    k_scan_tops<<<1, 128>>>();
    k_scan_add<<<(NN + 255)/256, 256>>>();
    k_fill<<<(NE + 255)/256, 256>>>(src, dst);
    k_molptr<<<(NN + 255)/256, 256>>>(mol_ids);
    k_embed<<<(NN*16 + 255)/256, 256>>>(atom_ids, emb_W);

    const int GG_GRID   = (NN + 63) / 64;
    const int GEMM_GRID = (NN + 127) / 128;
    for (int l = 0; l < NL; l++) {
        const float* xin = (l == 0) ? X0 : XS + (size_t)(l-1) * NN * D;
        k_gather_gemm<<<GG_GRID, 256>>>(xin, gin_W1 + (size_t)l*D*D, gin_b1 + l*D, T, NN);
        k_bnparam<<<1, D>>>(gin_g1 + l*D, gin_be1 + l*D, 1.0f / NN);
        k_gemm64<1,1,0><<<GEMM_GRID, 256>>>(T, gin_W2 + (size_t)l*D*D, gin_b2 + l*D,
                                            XS + (size_t)l*NN*D, NN);
    }

    k_jk<<<GEMM_GRID, 256>>>(jk_W, jk_b, X0, NN);

    k_pool_seg<<<(NM*16 + 255)/256, 256>>>(X0);

    k_gemm64<0,0,1><<<(NM + 127)/128, 256>>>(G, ffn_W1, ffn_b1, TG, NM);
    k_bnparam<<<1, D>>>(ffn_g, ffn_be, 1.0f / NM);

    k_final<<<(NM + 255)/256, 256>>>(ffn_W2, out_W, ffn_b2, out_b, out, NM);
}